// round 5
// baseline (speedup 1.0000x reference)
#include <cuda_runtime.h>
#include <cstdint>

#define B_DIM 32
#define IN_PLANES 128
#define PLANES 32

#define XS_PITCH 132
#define WT_PITCH 132
// xs row base in floats: quad index = (7r + i) mod 32 for b=4r+i -> distinct over r
#define XROW(b) ((b) * XS_PITCH + ((b) >> 2) * 12)
#define XS_SIZE (31 * XS_PITCH + 7 * 12 + IN_PLANES)   // 4304 floats (17216 B, 8B aligned)
#define WT_SIZE (31 * WT_PITCH + IN_PLANES)            // 4220 floats
#define PER_VOX (XS_SIZE + WT_SIZE)                    // 8524 floats = 34096 B

// packed f32x2 ops (full fp32 precision, 2x FFMA rate)
#define FMA2(a, xx, ww) asm("fma.rn.f32x2 %0, %1, %2, %0;" : "+l"(a) : "l"(xx), "l"(ww))
#define ADD2(d, a, b)   asm("add.rn.f32x2 %0, %1, %2;"  : "=l"(d) : "l"(a), "l"(b))

static __device__ __forceinline__ unsigned long long dal(double d) {
    return __double_as_longlong(d);
}

extern __shared__ float smem_dyn[];

__global__ __launch_bounds__(256, 3) void voxel_mlp_kernel(
    const float* __restrict__ x,        // [B, n_sel, 128]
    const int*   __restrict__ vidx,     // [n_sel]
    const float* __restrict__ w0,       // [n_vox, 128, 32]
    const float* __restrict__ b0,       // [n_vox, 32]
    const float* __restrict__ w1,       // [n_vox, 32] (last dim 1)
    const float* __restrict__ b1,       // [n_vox]
    float*       __restrict__ out,      // [B, n_sel]
    int n_sel)
{
    const int t    = threadIdx.x;
    const int half = t >> 7;            // 0: warps 0-3, 1: warps 4-7
    const int tl   = t & 127;           // thread within voxel (128)

    const int n = blockIdx.x * 2 + half;
    if (n >= n_sel) return;

    float* xs  = smem_dyn + half * PER_VOX;
    float* wsT = xs + XS_SIZE;

    const int v = vidx[n];
    const float* xg = x  + (size_t)n * IN_PLANES;
    const float* wg = w0 + (size_t)v * (IN_PLANES * PLANES);

    // ---- load x: 1024 float4, coalesced LDG.128 -> STS.128 (conflict-free) ----
    #pragma unroll
    for (int m = 0; m < 8; m++) {
        int j  = tl + 128 * m;
        int b  = j >> 5;        // warp-uniform row
        int c4 = j & 31;        // 16B chunk
        float4 val = *reinterpret_cast<const float4*>(xg + (size_t)b * n_sel * IN_PLANES + c4 * 4);
        *reinterpret_cast<float4*>(&xs[XROW(b) + c4 * 4]) = val;
    }

    // ---- load w0 [128][32]: register 4x4-block transpose into wsT[o][k], pitch 132 ----
    {
        const int l  = tl & 31;
        const int wv = tl >> 5;         // warp within voxel 0..3
        const int o4 = l >> 2;
        #pragma unroll
        for (int it = 0; it < 2; it++) {
            const int k0 = ((l & 3) << 2) + (wv << 4) + (it << 6);
            float4 f0 = *reinterpret_cast<const float4*>(wg + (k0 + 0) * PLANES + o4 * 4);
            float4 f1 = *reinterpret_cast<const float4*>(wg + (k0 + 1) * PLANES + o4 * 4);
            float4 f2 = *reinterpret_cast<const float4*>(wg + (k0 + 2) * PLANES + o4 * 4);
            float4 f3 = *reinterpret_cast<const float4*>(wg + (k0 + 3) * PLANES + o4 * 4);
            float4 t0 = make_float4(f0.x, f1.x, f2.x, f3.x);
            float4 t1 = make_float4(f0.y, f1.y, f2.y, f3.y);
            float4 t2 = make_float4(f0.z, f1.z, f2.z, f3.z);
            float4 t3 = make_float4(f0.w, f1.w, f2.w, f3.w);
            *reinterpret_cast<float4*>(&wsT[(4 * o4 + 0) * WT_PITCH + k0]) = t0;
            *reinterpret_cast<float4*>(&wsT[(4 * o4 + 1) * WT_PITCH + k0]) = t1;
            *reinterpret_cast<float4*>(&wsT[(4 * o4 + 2) * WT_PITCH + k0]) = t2;
            *reinterpret_cast<float4*>(&wsT[(4 * o4 + 3) * WT_PITCH + k0]) = t3;
        }
    }

    // per-voxel barrier (128 threads)
    asm volatile("bar.sync %0, %1;" :: "r"(half + 1), "r"(128) : "memory");

    // k-split: warps {0,1} -> k in [0,64), warps {2,3} -> k in [64,128)
    // within a k-half, 64 threads tile the 32x32 output: b in {4r..4r+3}, o in {c,c+8,c+16,c+24}
    const int kh = tl >> 6;             // k-half
    const int t2 = tl & 63;             // thread within k-half
    const int r  = t2 >> 3;             // 0..7
    const int c  = t2 & 7;              // 0..7

    const float* xb[4];
    const float* wb[4];
    #pragma unroll
    for (int i = 0; i < 4; i++)  xb[i]  = xs  + XROW(4 * r + i) + kh * 64;
    #pragma unroll
    for (int jo = 0; jo < 4; jo++) wb[jo] = wsT + (c + 8 * jo) * WT_PITCH + kh * 64;

    unsigned long long acc[4][4];
    #pragma unroll
    for (int i = 0; i < 4; i++)
        #pragma unroll
        for (int jo = 0; jo < 4; jo++)
            acc[i][jo] = 0ULL;

    // ---- main GEMM over this warp's k-half: 16 chunks of 4 k ----
    #pragma unroll 8
    for (int k4 = 0; k4 < 16; k4++) {
        unsigned long long xk0[4], xk1[4], wk0[4], wk1[4];
        #pragma unroll
        for (int i = 0; i < 4; i++) {
            double2 d = *reinterpret_cast<const double2*>(xb[i] + k4 * 4);
            xk0[i] = dal(d.x);
            xk1[i] = dal(d.y);
        }
        #pragma unroll
        for (int jo = 0; jo < 4; jo++) {
            double2 d = *reinterpret_cast<const double2*>(wb[jo] + k4 * 4);
            wk0[jo] = dal(d.x);
            wk1[jo] = dal(d.y);
        }
        #pragma unroll
        for (int i = 0; i < 4; i++)
            #pragma unroll
            for (int jo = 0; jo < 4; jo++) {
                FMA2(acc[i][jo], xk0[i], wk0[jo]);
                FMA2(acc[i][jo], xk1[i], wk1[jo]);
            }
    }

    // ---- combine k-halves via smem (reuse wsT region, now dead) ----
    unsigned long long* xchg = reinterpret_cast<unsigned long long*>(wsT);
    asm volatile("bar.sync %0, %1;" :: "r"(half + 1), "r"(128) : "memory");
    if (kh == 1) {
        #pragma unroll
        for (int i = 0; i < 4; i++)
            #pragma unroll
            for (int jo = 0; jo < 4; jo++)
                xchg[(i * 4 + jo) * 64 + t2] = acc[i][jo];   // [j][t2]: conflict-free
    }
    asm volatile("bar.sync %0, %1;" :: "r"(half + 1), "r"(128) : "memory");
    if (kh == 1) return;

    #pragma unroll
    for (int i = 0; i < 4; i++)
        #pragma unroll
        for (int jo = 0; jo < 4; jo++)
            ADD2(acc[i][jo], acc[i][jo], xchg[(i * 4 + jo) * 64 + t2]);

    // ---- epilogue: /128 + b0, exact-erf GELU, dot w1, /32 + b1 ----
    const float inv_in = 1.0f / (float)IN_PLANES;
    const float inv_p  = 1.0f / (float)PLANES;

    float b0v[4], w1v[4];
    #pragma unroll
    for (int jo = 0; jo < 4; jo++) {
        int o = c + 8 * jo;
        b0v[jo] = b0[(size_t)v * PLANES + o];
        w1v[jo] = w1[(size_t)v * PLANES + o];
    }
    const float b1v = b1[v];

    float s[4];
    #pragma unroll
    for (int i = 0; i < 4; i++) {
        s[i] = 0.0f;
        #pragma unroll
        for (int jo = 0; jo < 4; jo++) {
            unsigned long long a = acc[i][jo];
            float lo = __uint_as_float((unsigned)(a & 0xffffffffULL));
            float hi = __uint_as_float((unsigned)(a >> 32));
            float h  = (lo + hi) * inv_in + b0v[jo];
            float g  = h * normcdff(h);          // exact-erf GELU
            s[i] += g * w1v[jo];
        }
    }

    #pragma unroll
    for (int i = 0; i < 4; i++) {
        s[i] += __shfl_xor_sync(0xffffffffu, s[i], 1);
        s[i] += __shfl_xor_sync(0xffffffffu, s[i], 2);
        s[i] += __shfl_xor_sync(0xffffffffu, s[i], 4);
    }

    if (c == 0) {
        #pragma unroll
        for (int i = 0; i < 4; i++) {
            int b = 4 * r + i;
            out[(size_t)b * n_sel + n] = s[i] * inv_p + b1v;
        }
    }
}

extern "C" void kernel_launch(void* const* d_in, const int* in_sizes, int n_in,
                              void* d_out, int out_size) {
    const float* x    = (const float*)d_in[0];
    const int*   vidx = (const int*)  d_in[1];
    const float* w0   = (const float*)d_in[2];
    const float* b0   = (const float*)d_in[3];
    const float* w1   = (const float*)d_in[4];
    const float* b1   = (const float*)d_in[5];
    float*       out  = (float*)d_out;

    const int n_sel = in_sizes[1];
    const int smem_bytes = 2 * PER_VOX * (int)sizeof(float);   // 68192 B

    static int configured = -1;
    if (configured != smem_bytes) {
        cudaFuncSetAttribute(voxel_mlp_kernel,
                             cudaFuncAttributeMaxDynamicSharedMemorySize, smem_bytes);
        configured = smem_bytes;
    }

    const int grid = (n_sel + 1) / 2;
    voxel_mlp_kernel<<<grid, 256, smem_bytes>>>(x, vidx, w0, b0, w1, b1, out, n_sel);
}